// round 2
// baseline (speedup 1.0000x reference)
#include <cuda_runtime.h>
#include <math.h>

#define BATCH 2
#define CH    512
#define CQ    64
#define NPIX  4096

// ---------------- static scratch (allocation-free rule) ----------------
__device__ float g_S12[(size_t)BATCH * NPIX * NPIX];   // logits12 -> att (in place)
__device__ float g_S21[(size_t)BATCH * NPIX * NPIX];   // logits21
__device__ float g_A1[BATCH * CQ * NPIX];
__device__ float g_A2[BATCH * CQ * NPIX];
__device__ float g_B1[BATCH * CQ * NPIX];
__device__ float g_B2[BATCH * CQ * NPIX];
__device__ float g_F [BATCH * CH * NPIX];
__device__ float g_xc[BATCH * CH * NPIX];
__device__ float g_scal[4];

// ---------------- tiny scalar prep ----------------
__global__ void scal_kernel(const float* a, const float* b) {
    g_scal[0] = a[0];
    g_scal[1] = b[0];
    g_scal[2] = a[0] + b[0];
}

// xc = alpha*x1 + beta*x2 (vectorized)
__global__ void ewise_combine(const float* __restrict__ x1,
                              const float* __restrict__ x2,
                              float* __restrict__ xc, int n4) {
    float a = g_scal[0], b = g_scal[1];
    int i = blockIdx.x * blockDim.x + threadIdx.x;
    if (i < n4) {
        float4 u = ((const float4*)x1)[i];
        float4 v = ((const float4*)x2)[i];
        float4 w;
        w.x = a * u.x + b * v.x;
        w.y = a * u.y + b * v.y;
        w.z = a * u.z + b * v.z;
        w.w = a * u.w + b * v.w;
        ((float4*)xc)[i] = w;
    }
}

// ---------------- generic strided SGEMM ----------------
// C[m,n] = sum_k A[m,k]*B[k,n] (+ bias[m] * (useScale ? (alpha+beta) : 1))
template<int BM, int BN, int BK, int TM, int TN>
__global__ void __launch_bounds__((BM / TM) * (BN / TN))
sgemm(const float* __restrict__ A, const float* __restrict__ B,
      float* __restrict__ C,
      int M, int Nn, int K,
      long sAm, long sAk, long bsA,
      long sBk, long sBn, long bsB,
      long sCm, long sCn, long bsC,
      const float* __restrict__ bias, int useScale)
{
    constexpr int THREADS = (BM / TM) * (BN / TN);
    __shared__ float As[BK][BM + 1];
    __shared__ float Bs[BK][BN + 1];

    const float* Ab = A + bsA * blockIdx.z;
    const float* Bb = B + bsB * blockIdx.z;
    float*       Cb = C + bsC * blockIdx.z;

    const int row0 = blockIdx.y * BM;
    const int col0 = blockIdx.x * BN;
    const int tid  = threadIdx.x;
    const int tx   = tid % (BN / TN);
    const int ty   = tid / (BN / TN);

    float acc[TM][TN];
#pragma unroll
    for (int i = 0; i < TM; i++)
#pragma unroll
        for (int j = 0; j < TN; j++) acc[i][j] = 0.0f;

    const bool aKfast = (sAk == 1);
    const bool bNfast = (sBn == 1);

    for (int k0 = 0; k0 < K; k0 += BK) {
        // load A tile
#pragma unroll
        for (int idx = tid; idx < BK * BM; idx += THREADS) {
            int m, kk;
            if (aKfast) { kk = idx % BK; m = idx / BK; }
            else        { m = idx % BM; kk = idx / BM; }
            As[kk][m] = Ab[(long)(row0 + m) * sAm + (long)(k0 + kk) * sAk];
        }
        // load B tile
#pragma unroll
        for (int idx = tid; idx < BK * BN; idx += THREADS) {
            int nn, kk;
            if (bNfast) { nn = idx % BN; kk = idx / BN; }
            else        { kk = idx % BK; nn = idx / BK; }
            Bs[kk][nn] = Bb[(long)(k0 + kk) * sBk + (long)(col0 + nn) * sBn];
        }
        __syncthreads();

#pragma unroll
        for (int kk = 0; kk < BK; kk++) {
            float av[TM], bv[TN];
#pragma unroll
            for (int i = 0; i < TM; i++) av[i] = As[kk][ty * TM + i];
#pragma unroll
            for (int j = 0; j < TN; j++) bv[j] = Bs[kk][tx * TN + j];
#pragma unroll
            for (int i = 0; i < TM; i++)
#pragma unroll
                for (int j = 0; j < TN; j++) acc[i][j] += av[i] * bv[j];
        }
        __syncthreads();
    }

    const float bscale = useScale ? g_scal[2] : 1.0f;
#pragma unroll
    for (int i = 0; i < TM; i++) {
        const int m = row0 + ty * TM + i;
        const float bv = bias ? bias[m] * bscale : 0.0f;
#pragma unroll
        for (int j = 0; j < TN; j++) {
            const int nn = col0 + tx * TN + j;
            Cb[(long)m * sCm + (long)nn * sCn] = acc[i][j] + bv;
        }
    }
}

// ---------------- fused double-softmax abs-diff ----------------
// att[row, m] = | softmax(S12[row,:])[m] - softmax(S21[row,:])[m] |
// written back into g_S12. One block per row (B*N rows).
__global__ void __launch_bounds__(256) softdiff_kernel() {
    const long row = blockIdx.x;
    float*       p12 = g_S12 + row * (long)NPIX;
    const float* p21 = g_S21 + row * (long)NPIX;
    const int t = threadIdx.x;
    constexpr int PER = NPIX / 256;   // 16

    float v12[PER], v21[PER];
    float mx12 = -1e30f, mx21 = -1e30f;
#pragma unroll
    for (int i = 0; i < PER; i++) {
        v12[i] = p12[t + i * 256];
        v21[i] = p21[t + i * 256];
        mx12 = fmaxf(mx12, v12[i]);
        mx21 = fmaxf(mx21, v21[i]);
    }

    __shared__ float red[2][8];
#pragma unroll
    for (int o = 16; o > 0; o >>= 1) {
        mx12 = fmaxf(mx12, __shfl_xor_sync(0xffffffffu, mx12, o));
        mx21 = fmaxf(mx21, __shfl_xor_sync(0xffffffffu, mx21, o));
    }
    if ((t & 31) == 0) { red[0][t >> 5] = mx12; red[1][t >> 5] = mx21; }
    __syncthreads();
    mx12 = red[0][0]; mx21 = red[1][0];
#pragma unroll
    for (int w = 1; w < 8; w++) {
        mx12 = fmaxf(mx12, red[0][w]);
        mx21 = fmaxf(mx21, red[1][w]);
    }
    __syncthreads();

    float s12 = 0.0f, s21 = 0.0f;
#pragma unroll
    for (int i = 0; i < PER; i++) {
        v12[i] = __expf(v12[i] - mx12);
        v21[i] = __expf(v21[i] - mx21);
        s12 += v12[i];
        s21 += v21[i];
    }
#pragma unroll
    for (int o = 16; o > 0; o >>= 1) {
        s12 += __shfl_xor_sync(0xffffffffu, s12, o);
        s21 += __shfl_xor_sync(0xffffffffu, s21, o);
    }
    if ((t & 31) == 0) { red[0][t >> 5] = s12; red[1][t >> 5] = s21; }
    __syncthreads();
    s12 = red[0][0]; s21 = red[1][0];
#pragma unroll
    for (int w = 1; w < 8; w++) { s12 += red[0][w]; s21 += red[1][w]; }

    const float i12 = 1.0f / s12;
    const float i21 = 1.0f / s21;
#pragma unroll
    for (int i = 0; i < PER; i++)
        p12[t + i * 256] = fabsf(v12[i] * i12 - v21[i] * i21);
}

// ---------------- launch ----------------
extern "C" void kernel_launch(void* const* d_in, const int* in_sizes, int n_in,
                              void* d_out, int out_size) {
    const float* x1    = (const float*)d_in[0];
    const float* x2    = (const float*)d_in[1];
    const float* Wb    = (const float*)d_in[2];
    const float* bb    = (const float*)d_in[3];
    const float* Wc    = (const float*)d_in[4];
    const float* bc    = (const float*)d_in[5];
    const float* Wdd   = (const float*)d_in[6];
    const float* bd    = (const float*)d_in[7];
    const float* alpha = (const float*)d_in[8];
    const float* beta  = (const float*)d_in[9];
    float* out = (float*)d_out;

    float *S12, *S21, *A1, *A2, *B1, *B2, *F, *xc;
    cudaGetSymbolAddress((void**)&S12, g_S12);
    cudaGetSymbolAddress((void**)&S21, g_S21);
    cudaGetSymbolAddress((void**)&A1,  g_A1);
    cudaGetSymbolAddress((void**)&A2,  g_A2);
    cudaGetSymbolAddress((void**)&B1,  g_B1);
    cudaGetSymbolAddress((void**)&B2,  g_B2);
    cudaGetSymbolAddress((void**)&F,   g_F);
    cudaGetSymbolAddress((void**)&xc,  g_xc);

    scal_kernel<<<1, 1>>>(alpha, beta);

    const int n4 = BATCH * CH * NPIX / 4;
    ewise_combine<<<(n4 + 255) / 256, 256>>>(x1, x2, xc, n4);

    const long bsX = (long)CH * NPIX;   // batch stride for x
    const long bsQ = (long)CQ * NPIX;   // batch stride for 64-ch projections
    const long bsS = (long)NPIX * NPIX; // batch stride for logits/att

    // 64-channel projections: Y[o,n] = W[o,c] X[c,n] + b[o]
    dim3 gridP(NPIX / 128, 1, BATCH);
    sgemm<64, 128, 16, 4, 8><<<gridP, 256>>>(Wb, x1, A1, CQ, NPIX, CH,
        (long)CH, 1L, 0L,   (long)NPIX, 1L, bsX,   (long)NPIX, 1L, bsQ, bb, 0);
    sgemm<64, 128, 16, 4, 8><<<gridP, 256>>>(Wb, x2, A2, CQ, NPIX, CH,
        (long)CH, 1L, 0L,   (long)NPIX, 1L, bsX,   (long)NPIX, 1L, bsQ, bb, 0);
    sgemm<64, 128, 16, 4, 8><<<gridP, 256>>>(Wc, x1, B1, CQ, NPIX, CH,
        (long)CH, 1L, 0L,   (long)NPIX, 1L, bsX,   (long)NPIX, 1L, bsQ, bc, 0);
    sgemm<64, 128, 16, 4, 8><<<gridP, 256>>>(Wc, x2, B2, CQ, NPIX, CH,
        (long)CH, 1L, 0L,   (long)NPIX, 1L, bsX,   (long)NPIX, 1L, bsQ, bc, 0);

    // F = Wdd @ xc + (alpha+beta)*bd   [512 x 4096]
    dim3 gridF(NPIX / 128, CH / 128, BATCH);
    sgemm<128, 128, 16, 8, 8><<<gridF, 256>>>(Wdd, xc, F, CH, NPIX, CH,
        (long)CH, 1L, 0L,   (long)NPIX, 1L, bsX,   (long)NPIX, 1L, bsX, bd, 1);

    // logits: S12[n,m] = sum_c A1[c,n] * B2[c,m]
    dim3 gridS(NPIX / 128, NPIX / 128, BATCH);
    sgemm<128, 128, 16, 8, 8><<<gridS, 256>>>(A1, B2, S12, NPIX, NPIX, CQ,
        1L, (long)NPIX, bsQ,   (long)NPIX, 1L, bsQ,   (long)NPIX, 1L, bsS, nullptr, 0);
    sgemm<128, 128, 16, 8, 8><<<gridS, 256>>>(A2, B1, S21, NPIX, NPIX, CQ,
        1L, (long)NPIX, bsQ,   (long)NPIX, 1L, bsQ,   (long)NPIX, 1L, bsS, nullptr, 0);

    // att = |softmax(S12) - softmax(S21)| row-wise (in place into S12)
    softdiff_kernel<<<BATCH * NPIX, 256>>>();

    // out[c,n] = sum_m F[c,m] * att[n,m]
    dim3 gridO(NPIX / 128, CH / 128, BATCH);
    sgemm<128, 128, 16, 8, 8><<<gridO, 256>>>(F, S12, out, CH, NPIX, NPIX,
        (long)NPIX, 1L, bsX,   1L, (long)NPIX, bsS,   (long)NPIX, 1L, bsX, nullptr, 0);
}

// round 4
// speedup vs baseline: 3.1137x; 3.1137x over previous
#include <cuda_runtime.h>
#include <cuda_bf16.h>
#include <math.h>
#include <stdint.h>

#define BATCH 2
#define CH    512
#define CQ    64
#define NPIX  4096

typedef __nv_bfloat16 bf16;

// ---------------- static scratch ----------------
__device__ __align__(128) bf16  g_xTh[4L * NPIX * CH];   // [which*2+b][n][c] hi
__device__ __align__(128) bf16  g_xTl[4L * NPIX * CH];
__device__ __align__(128) bf16  g_xcTh[2L * NPIX * CH];  // [b][n][c]
__device__ __align__(128) bf16  g_xcTl[2L * NPIX * CH];
__device__ __align__(128) bf16  g_Wbch[128 * CH];        // [o(128)][c] (Wb;Wc)
__device__ __align__(128) bf16  g_Wbcl[128 * CH];
__device__ __align__(128) bf16  g_Wdh[CH * CH];
__device__ __align__(128) bf16  g_Wdl[CH * CH];
__device__ __align__(128) float g_P [4L * NPIX * 128];   // [which*2+b][n][o]
__device__ __align__(128) bf16  g_Ph[4L * NPIX * 128];
__device__ __align__(128) bf16  g_Pl[4L * NPIX * 128];
__device__ __align__(128) float g_F [(long)BATCH * CH * NPIX];  // [b][c][n]
__device__ __align__(128) bf16  g_Fh[(long)BATCH * CH * NPIX];
__device__ __align__(128) bf16  g_Fl[(long)BATCH * CH * NPIX];
__device__ __align__(128) float g_S12[(size_t)BATCH * NPIX * NPIX];
__device__ __align__(128) float g_S21[(size_t)BATCH * NPIX * NPIX];
__device__ __align__(128) bf16  g_Ah[(size_t)BATCH * NPIX * NPIX];
__device__ __align__(128) bf16  g_Al[(size_t)BATCH * NPIX * NPIX];
__device__ float g_scal[4];
__device__ float g_bias2[128];

// ---------------- prep: scalars + packed per-col bias ----------------
__global__ void prep_kernel(const float* bb, const float* bc,
                            const float* a, const float* b) {
    int t = threadIdx.x;
    if (t < 64)       g_bias2[t] = bb[t];
    else if (t < 128) g_bias2[t] = bc[t - 64];
    if (t == 0) { g_scal[0] = a[0]; g_scal[1] = b[0]; g_scal[2] = a[0] + b[0]; }
}

// ---------------- generic fp32 -> bf16 hi/lo split ----------------
__global__ void split_kernel(const float* __restrict__ src,
                             bf16* __restrict__ hi, bf16* __restrict__ lo, int n) {
    int i = blockIdx.x * blockDim.x + threadIdx.x;
    if (i < n) {
        float v = src[i];
        bf16 h = __float2bfloat16(v);
        hi[i] = h;
        lo[i] = __float2bfloat16(v - __bfloat162float(h));
    }
}

// concat [Wb;Wc] -> hi/lo
__global__ void wbc_split_kernel(const float* __restrict__ Wb,
                                 const float* __restrict__ Wc) {
    int i = blockIdx.x * blockDim.x + threadIdx.x;
    if (i < 128 * CH) {
        float v = (i < 64 * CH) ? Wb[i] : Wc[i - 64 * CH];
        bf16 h = __float2bfloat16(v);
        g_Wbch[i] = h;
        g_Wbcl[i] = __float2bfloat16(v - __bfloat162float(h));
    }
}

// ---------------- combine + transpose + split (x1, x2 -> x1T,x2T,xcT hi/lo) ----
__global__ void __launch_bounds__(256) transcomb_kernel(
    const float* __restrict__ x1, const float* __restrict__ x2) {
    __shared__ float t1[32][33], t2[32][33];
    const int b  = blockIdx.z;
    const int n0 = blockIdx.x * 32;
    const int k0 = blockIdx.y * 32;
    const int tx = threadIdx.x, ty = threadIdx.y;
    const float al = g_scal[0], be = g_scal[1];

    const long inb = (long)b * CH * NPIX;
#pragma unroll
    for (int it = 0; it < 4; it++) {
        int ki = ty + it * 8;
        t1[ki][tx] = x1[inb + (long)(k0 + ki) * NPIX + n0 + tx];
        t2[ki][tx] = x2[inb + (long)(k0 + ki) * NPIX + n0 + tx];
    }
    __syncthreads();

#pragma unroll
    for (int it = 0; it < 4; it++) {
        int ni = ty + it * 8;
        float v1 = t1[tx][ni];
        float v2 = t2[tx][ni];
        float vc = al * v1 + be * v2;
        long o1 = ((long)b * NPIX + n0 + ni) * CH + k0 + tx;           // which=0
        long o2 = ((long)(2 + b) * NPIX + n0 + ni) * CH + k0 + tx;     // which=1
        long oc = ((long)b * NPIX + n0 + ni) * CH + k0 + tx;
        bf16 h1 = __float2bfloat16(v1);
        bf16 h2 = __float2bfloat16(v2);
        bf16 hc = __float2bfloat16(vc);
        g_xTh[o1] = h1; g_xTl[o1] = __float2bfloat16(v1 - __bfloat162float(h1));
        g_xTh[o2] = h2; g_xTl[o2] = __float2bfloat16(v2 - __bfloat162float(h2));
        g_xcTh[oc] = hc; g_xcTl[oc] = __float2bfloat16(vc - __bfloat162float(hc));
    }
}

// ---------------- fused double-softmax abs-diff -> bf16 hi/lo ----------------
__global__ void __launch_bounds__(256) softdiff_kernel() {
    const long row = blockIdx.x;
    const float* p12 = g_S12 + row * (long)NPIX;
    const float* p21 = g_S21 + row * (long)NPIX;
    bf16* oh = g_Ah + row * (long)NPIX;
    bf16* ol = g_Al + row * (long)NPIX;
    const int t = threadIdx.x;
    constexpr int PER = NPIX / 256;

    float v12[PER], v21[PER];
    float mx12 = -1e30f, mx21 = -1e30f;
#pragma unroll
    for (int i = 0; i < PER; i++) {
        v12[i] = p12[t + i * 256];
        v21[i] = p21[t + i * 256];
        mx12 = fmaxf(mx12, v12[i]);
        mx21 = fmaxf(mx21, v21[i]);
    }
    __shared__ float red[2][8];
#pragma unroll
    for (int o = 16; o > 0; o >>= 1) {
        mx12 = fmaxf(mx12, __shfl_xor_sync(0xffffffffu, mx12, o));
        mx21 = fmaxf(mx21, __shfl_xor_sync(0xffffffffu, mx21, o));
    }
    if ((t & 31) == 0) { red[0][t >> 5] = mx12; red[1][t >> 5] = mx21; }
    __syncthreads();
    mx12 = red[0][0]; mx21 = red[1][0];
#pragma unroll
    for (int w = 1; w < 8; w++) {
        mx12 = fmaxf(mx12, red[0][w]);
        mx21 = fmaxf(mx21, red[1][w]);
    }
    __syncthreads();

    float s12 = 0.0f, s21 = 0.0f;
#pragma unroll
    for (int i = 0; i < PER; i++) {
        v12[i] = __expf(v12[i] - mx12);
        v21[i] = __expf(v21[i] - mx21);
        s12 += v12[i]; s21 += v21[i];
    }
#pragma unroll
    for (int o = 16; o > 0; o >>= 1) {
        s12 += __shfl_xor_sync(0xffffffffu, s12, o);
        s21 += __shfl_xor_sync(0xffffffffu, s21, o);
    }
    if ((t & 31) == 0) { red[0][t >> 5] = s12; red[1][t >> 5] = s21; }
    __syncthreads();
    s12 = red[0][0]; s21 = red[1][0];
#pragma unroll
    for (int w = 1; w < 8; w++) { s12 += red[0][w]; s21 += red[1][w]; }

    const float i12 = 1.0f / s12;
    const float i21 = 1.0f / s21;
#pragma unroll
    for (int i = 0; i < PER; i++) {
        float att = fabsf(v12[i] * i12 - v21[i] * i21);
        bf16 h = __float2bfloat16(att);
        oh[t + i * 256] = h;
        ol[t + i * 256] = __float2bfloat16(att - __bfloat162float(h));
    }
}

// ================= HMMA bf16 multi-term GEMM (mma.sync, sm_80 ISA) =========
// C[m,n] = sum_t sum_k A_t[m,k] * B_t[n,k]   (A, B K-major bf16)
// BM=BN=128, BK=32, 8 warps (4M x 2N), warp tile 32x64.
// BIASMODE: 0 none, 1 per-row bias[m]*g_scal[2], 2 per-col bias[n].

#define SM_STRIDE 40           // halves per smem row (80 B, conflict-free ldmatrix)
#define STAGE_H   (128 * SM_STRIDE)

__device__ __forceinline__ uint32_t smem_u32(const void* p) {
    uint32_t a;
    asm("{ .reg .u64 t; cvta.to.shared.u64 t, %1; cvt.u32.u64 %0, t; }" : "=r"(a) : "l"(p));
    return a;
}
__device__ __forceinline__ void cp16(uint32_t dst, const void* src) {
    asm volatile("cp.async.cg.shared.global [%0], [%1], 16;" :: "r"(dst), "l"(src));
}
__device__ __forceinline__ void ldsm4(uint32_t* r, uint32_t addr) {
    asm volatile("ldmatrix.sync.aligned.m8n8.x4.shared.b16 {%0,%1,%2,%3}, [%4];"
                 : "=r"(r[0]), "=r"(r[1]), "=r"(r[2]), "=r"(r[3]) : "r"(addr));
}
__device__ __forceinline__ void mma16816(float* d, const uint32_t* a, const uint32_t* b) {
    asm volatile(
        "mma.sync.aligned.m16n8k16.row.col.f32.bf16.bf16.f32 "
        "{%0,%1,%2,%3}, {%4,%5,%6,%7}, {%8,%9}, {%0,%1,%2,%3};"
        : "+f"(d[0]), "+f"(d[1]), "+f"(d[2]), "+f"(d[3])
        : "r"(a[0]), "r"(a[1]), "r"(a[2]), "r"(a[3]), "r"(b[0]), "r"(b[1]));
}

template<int BIASMODE>
__global__ void __launch_bounds__(256, 2) hgemm_kernel(
    const bf16* __restrict__ a0, const bf16* __restrict__ a1, const bf16* __restrict__ a2,
    const bf16* __restrict__ b0, const bf16* __restrict__ b1, const bf16* __restrict__ b2,
    int ktPerTerm, int nkt, int lda, int ldb, long bsA, long bsB,
    float* __restrict__ C, int ldc, long bsC, const float* __restrict__ bias)
{
    __shared__ __align__(16) bf16 smA[2 * STAGE_H];
    __shared__ __align__(16) bf16 smB[2 * STAGE_H];

    const int tid = threadIdx.x;
    const int wid = tid >> 5;
    const int lane = tid & 31;
    const int wm = wid >> 1;           // 0..3
    const int wn = wid & 1;            // 0..1
    const int m0 = blockIdx.y * 128;
    const int n0 = blockIdx.x * 128;
    const int z  = blockIdx.z;

    const uint32_t sA0 = smem_u32(smA);
    const uint32_t sB0 = smem_u32(smB);

    float acc[2][8][4];
#pragma unroll
    for (int i = 0; i < 2; i++)
#pragma unroll
        for (int j = 0; j < 8; j++)
#pragma unroll
            for (int q = 0; q < 4; q++) acc[i][j][q] = 0.0f;

    // per-thread load coords (2 chunks of 16B each per operand per stage)
    const int lrow0 = tid >> 2;            // 0..63
    const int lch0  = tid & 3;
    auto load_tile = [&](int g, int buf) {
        const int t  = g / ktPerTerm;
        const int k0 = (g - t * ktPerTerm) * 32;
        const bf16* Ap = (t == 0 ? a0 : (t == 1 ? a1 : a2)) + z * bsA + (long)m0 * lda + k0;
        const bf16* Bp = (t == 0 ? b0 : (t == 1 ? b1 : b2)) + z * bsB + (long)n0 * ldb + k0;
        const uint32_t da = sA0 + buf * (STAGE_H * 2);
        const uint32_t db = sB0 + buf * (STAGE_H * 2);
#pragma unroll
        for (int i = 0; i < 2; i++) {
            int row = lrow0 + i * 64;
            cp16(da + row * 80 + lch0 * 16, Ap + (long)row * lda + lch0 * 8);
            cp16(db + row * 80 + lch0 * 16, Bp + (long)row * ldb + lch0 * 8);
        }
        asm volatile("cp.async.commit_group;");
    };

    load_tile(0, 0);

    for (int g = 0; g < nkt; g++) {
        if (g + 1 < nkt) {
            load_tile(g + 1, (g + 1) & 1);
            asm volatile("cp.async.wait_group 1;");
        } else {
            asm volatile("cp.async.wait_group 0;");
        }
        __syncthreads();

        const uint32_t da = sA0 + (g & 1) * (STAGE_H * 2);
        const uint32_t db = sB0 + (g & 1) * (STAGE_H * 2);
#pragma unroll
        for (int ks = 0; ks < 2; ks++) {
            uint32_t af[2][4];
#pragma unroll
            for (int mt = 0; mt < 2; mt++) {
                int row = wm * 32 + mt * 16 + (lane & 15);
                int kc  = ks * 16 + (lane >> 4) * 8;
                ldsm4(af[mt], da + row * 80 + kc * 2);
            }
            uint32_t bfr[4][4];
#pragma unroll
            for (int p = 0; p < 4; p++) {
                int row = wn * 64 + p * 16 + (lane >> 4) * 8 + (lane & 7);
                int kc  = ks * 16 + ((lane >> 3) & 1) * 8;
                ldsm4(bfr[p], db + row * 80 + kc * 2);
            }
#pragma unroll
            for (int mt = 0; mt < 2; mt++)
#pragma unroll
                for (int p = 0; p < 4; p++) {
                    mma16816(acc[mt][2 * p],     af[mt], &bfr[p][0]);
                    mma16816(acc[mt][2 * p + 1], af[mt], &bfr[p][2]);
                }
        }
        __syncthreads();
    }

    // epilogue
    float* Cz = C + (long)z * bsC;
#pragma unroll
    for (int mt = 0; mt < 2; mt++) {
        const int mA = m0 + wm * 32 + mt * 16 + (lane >> 2);
        float bvA = 0.0f, bvB = 0.0f;
        if (BIASMODE == 1) { bvA = bias[mA] * g_scal[2]; bvB = bias[mA + 8] * g_scal[2]; }
#pragma unroll
        for (int nt = 0; nt < 8; nt++) {
            const int n = n0 + wn * 64 + nt * 8 + (lane & 3) * 2;
            float c0 = acc[mt][nt][0], c1 = acc[mt][nt][1];
            float c2 = acc[mt][nt][2], c3 = acc[mt][nt][3];
            if (BIASMODE == 1) { c0 += bvA; c1 += bvA; c2 += bvB; c3 += bvB; }
            if (BIASMODE == 2) {
                float b0v = bias[n], b1v = bias[n + 1];
                c0 += b0v; c1 += b1v; c2 += b0v; c3 += b1v;
            }
            float2 v0 = make_float2(c0, c1);
            float2 v1 = make_float2(c2, c3);
            *(float2*)(Cz + (long)mA * ldc + n)       = v0;
            *(float2*)(Cz + (long)(mA + 8) * ldc + n) = v1;
        }
    }
}

// ---------------- launch ----------------
extern "C" void kernel_launch(void* const* d_in, const int* in_sizes, int n_in,
                              void* d_out, int out_size) {
    const float* x1    = (const float*)d_in[0];
    const float* x2    = (const float*)d_in[1];
    const float* Wb    = (const float*)d_in[2];
    const float* bb    = (const float*)d_in[3];
    const float* Wc    = (const float*)d_in[4];
    const float* bc    = (const float*)d_in[5];
    const float* Wdd   = (const float*)d_in[6];
    const float* bd    = (const float*)d_in[7];
    const float* alpha = (const float*)d_in[8];
    const float* beta  = (const float*)d_in[9];
    float* out = (float*)d_out;

    bf16 *xTh, *xTl, *xcTh, *xcTl, *Wbch, *Wbcl, *Wdh, *Wdl, *Ph, *Pl, *Fh, *Fl, *Ah, *Al;
    float *P, *F, *S12, *S21, *bias2;
    cudaGetSymbolAddress((void**)&xTh,  g_xTh);
    cudaGetSymbolAddress((void**)&xTl,  g_xTl);
    cudaGetSymbolAddress((void**)&xcTh, g_xcTh);
    cudaGetSymbolAddress((void**)&xcTl, g_xcTl);
    cudaGetSymbolAddress((void**)&Wbch, g_Wbch);
    cudaGetSymbolAddress((void**)&Wbcl, g_Wbcl);
    cudaGetSymbolAddress((void**)&Wdh,  g_Wdh);
    cudaGetSymbolAddress((void**)&Wdl,  g_Wdl);
    cudaGetSymbolAddress((void**)&P,    g_P);
    cudaGetSymbolAddress((void**)&Ph,   g_Ph);
    cudaGetSymbolAddress((void**)&Pl,   g_Pl);
    cudaGetSymbolAddress((void**)&F,    g_F);
    cudaGetSymbolAddress((void**)&Fh,   g_Fh);
    cudaGetSymbolAddress((void**)&Fl,   g_Fl);
    cudaGetSymbolAddress((void**)&S12,  g_S12);
    cudaGetSymbolAddress((void**)&S21,  g_S21);
    cudaGetSymbolAddress((void**)&Ah,   g_Ah);
    cudaGetSymbolAddress((void**)&Al,   g_Al);
    cudaGetSymbolAddress((void**)&bias2, g_bias2);

    // scalars + bias pack
    prep_kernel<<<1, 128>>>(bb, bc, alpha, beta);

    // x transposes + combine + splits
    dim3 gT(NPIX / 32, CH / 32, BATCH);
    transcomb_kernel<<<gT, dim3(32, 8)>>>(x1, x2);

    // weight splits
    wbc_split_kernel<<<(128 * CH + 255) / 256, 256>>>(Wb, Wc);
    split_kernel<<<(CH * CH + 255) / 256, 256>>>(Wdd, Wdh, Wdl, CH * CH);

    const long bsXT = (long)NPIX * CH;       // 2097152
    const long bsP  = (long)NPIX * 128;      // 524288
    const long bsF  = (long)CH * NPIX;       // 2097152
    const long bsS  = (long)NPIX * NPIX;     // 16777216

    // P^T = x^T @ Wbc^T  (M=4096, N=128, K=512), z = which*2+batch, bias per-col
    hgemm_kernel<2><<<dim3(1, NPIX / 128, 4), 256>>>(
        xTh, xTl, xTh,  Wbch, Wbch, Wbcl,
        CH / 32, 3 * CH / 32, CH, CH, bsXT, 0L,
        P, 128, bsP, bias2);

    split_kernel<<<(4 * (int)bsP + 255) / 256, 256>>>(P, Ph, Pl, 4 * (int)bsP);

    // F = Wdd @ xc + (a+b)*bd  (M=512, N=4096, K=512), z=batch, bias per-row
    hgemm_kernel<1><<<dim3(NPIX / 128, CH / 128, BATCH), 256>>>(
        Wdh, Wdl, Wdh,  xcTh, xcTh, xcTl,
        CH / 32, 3 * CH / 32, CH, CH, 0L, bsXT,
        F, NPIX, bsF, bd);

    split_kernel<<<(BATCH * (int)bsF + 255) / 256, 256>>>(F, Fh, Fl, BATCH * (int)bsF);

    // logits S12[n,m] = A1[n,:]·B2[m,:]  (M=N=4096, K=64)
    // A1 = P[0..1] cols 0-63 ; B2 = P[2..3] cols 64-127
    dim3 gS(NPIX / 128, NPIX / 128, BATCH);
    hgemm_kernel<0><<<gS, 256>>>(
        Ph, Pl, Ph,  Ph + 2 * bsP + 64, Ph + 2 * bsP + 64, Pl + 2 * bsP + 64,
        2, 6, 128, 128, bsP, bsP,
        S12, NPIX, bsS, nullptr);
    // S21: A2 = P[2..3] cols 0-63 ; B1 = P[0..1] cols 64-127
    hgemm_kernel<0><<<gS, 256>>>(
        Ph + 2 * bsP, Pl + 2 * bsP, Ph + 2 * bsP,  Ph + 64, Ph + 64, Pl + 64,
        2, 6, 128, 128, bsP, bsP,
        S21, NPIX, bsS, nullptr);

    // att = |softmax(S12)-softmax(S21)| -> bf16 hi/lo
    softdiff_kernel<<<BATCH * NPIX, 256>>>();

    // out[c,n] = sum_m F[c,m]*att[n,m]  (M=512, N=4096, K=3*4096)
    hgemm_kernel<0><<<dim3(NPIX / 128, CH / 128, BATCH), 256>>>(
        Fh, Fl, Fh,  Ah, Ah, Al,
        NPIX / 32, 3 * NPIX / 32, NPIX, NPIX, bsF, bsS,
        out, NPIX, bsF, nullptr);
}

// round 5
// speedup vs baseline: 3.3398x; 1.0726x over previous
#include <cuda_runtime.h>
#include <cuda_bf16.h>
#include <math.h>
#include <stdint.h>

#define BATCH 2
#define CH    512
#define CQ    64
#define NPIX  4096

typedef __nv_bfloat16 bf16;

// ---------------- static scratch ----------------
__device__ __align__(128) bf16  g_xTh[4L * NPIX * CH];   // [which*2+b][n][c] hi
__device__ __align__(128) bf16  g_xTl[4L * NPIX * CH];
__device__ __align__(128) bf16  g_xcTh[2L * NPIX * CH];  // [b][n][c]
__device__ __align__(128) bf16  g_xcTl[2L * NPIX * CH];
__device__ __align__(128) bf16  g_Wbch[128 * CH];        // [o(128)][c] (Wb;Wc)
__device__ __align__(128) bf16  g_Wbcl[128 * CH];
__device__ __align__(128) bf16  g_Wdh[CH * CH];
__device__ __align__(128) bf16  g_Wdl[CH * CH];
__device__ __align__(128) bf16  g_Ph[4L * NPIX * 128];   // [which*2+b][n][o]
__device__ __align__(128) bf16  g_Pl[4L * NPIX * 128];
__device__ __align__(128) bf16  g_Fh[(long)BATCH * CH * NPIX];  // [b][c][n]
__device__ __align__(128) bf16  g_Fl[(long)BATCH * CH * NPIX];
__device__ __align__(128) float g_S12[(size_t)BATCH * NPIX * NPIX];
__device__ __align__(128) float g_S21[(size_t)BATCH * NPIX * NPIX];
__device__ __align__(128) bf16  g_Ah[(size_t)BATCH * NPIX * NPIX];
__device__ __align__(128) bf16  g_Al[(size_t)BATCH * NPIX * NPIX];
__device__ float g_scal[4];
__device__ float g_bias2[128];

// ---------------- prep: scalars + packed per-col bias ----------------
__global__ void prep_kernel(const float* bb, const float* bc,
                            const float* a, const float* b) {
    int t = threadIdx.x;
    if (t < 64)       g_bias2[t] = bb[t];
    else if (t < 128) g_bias2[t] = bc[t - 64];
    if (t == 0) { g_scal[0] = a[0]; g_scal[1] = b[0]; g_scal[2] = a[0] + b[0]; }
}

// ---------------- fp32 -> bf16 hi/lo split (weights only) ----------------
__global__ void split_kernel(const float* __restrict__ src,
                             bf16* __restrict__ hi, bf16* __restrict__ lo, int n) {
    int i = blockIdx.x * blockDim.x + threadIdx.x;
    if (i < n) {
        float v = src[i];
        bf16 h = __float2bfloat16(v);
        hi[i] = h;
        lo[i] = __float2bfloat16(v - __bfloat162float(h));
    }
}

__global__ void wbc_split_kernel(const float* __restrict__ Wb,
                                 const float* __restrict__ Wc) {
    int i = blockIdx.x * blockDim.x + threadIdx.x;
    if (i < 128 * CH) {
        float v = (i < 64 * CH) ? Wb[i] : Wc[i - 64 * CH];
        bf16 h = __float2bfloat16(v);
        g_Wbch[i] = h;
        g_Wbcl[i] = __float2bfloat16(v - __bfloat162float(h));
    }
}

// ---------------- combine + transpose + split ----------------
__global__ void __launch_bounds__(256) transcomb_kernel(
    const float* __restrict__ x1, const float* __restrict__ x2) {
    __shared__ float t1[32][33], t2[32][33];
    const int b  = blockIdx.z;
    const int n0 = blockIdx.x * 32;
    const int k0 = blockIdx.y * 32;
    const int tx = threadIdx.x, ty = threadIdx.y;
    const float al = g_scal[0], be = g_scal[1];

    const long inb = (long)b * CH * NPIX;
#pragma unroll
    for (int it = 0; it < 4; it++) {
        int ki = ty + it * 8;
        t1[ki][tx] = x1[inb + (long)(k0 + ki) * NPIX + n0 + tx];
        t2[ki][tx] = x2[inb + (long)(k0 + ki) * NPIX + n0 + tx];
    }
    __syncthreads();

#pragma unroll
    for (int it = 0; it < 4; it++) {
        int ni = ty + it * 8;
        float v1 = t1[tx][ni];
        float v2 = t2[tx][ni];
        float vc = al * v1 + be * v2;
        long o1 = ((long)b * NPIX + n0 + ni) * CH + k0 + tx;
        long o2 = ((long)(2 + b) * NPIX + n0 + ni) * CH + k0 + tx;
        long oc = ((long)b * NPIX + n0 + ni) * CH + k0 + tx;
        bf16 h1 = __float2bfloat16(v1);
        bf16 h2 = __float2bfloat16(v2);
        bf16 hc = __float2bfloat16(vc);
        g_xTh[o1] = h1; g_xTl[o1] = __float2bfloat16(v1 - __bfloat162float(h1));
        g_xTh[o2] = h2; g_xTl[o2] = __float2bfloat16(v2 - __bfloat162float(h2));
        g_xcTh[oc] = hc; g_xcTl[oc] = __float2bfloat16(vc - __bfloat162float(hc));
    }
}

// ---------------- fused double-softmax abs-diff -> bf16 hi/lo ----------------
__global__ void __launch_bounds__(256) softdiff_kernel() {
    const long row = blockIdx.x;
    const float* p12 = g_S12 + row * (long)NPIX;
    const float* p21 = g_S21 + row * (long)NPIX;
    bf16* oh = g_Ah + row * (long)NPIX;
    bf16* ol = g_Al + row * (long)NPIX;
    const int t = threadIdx.x;
    constexpr int PER = NPIX / 256;

    float v12[PER], v21[PER];
    float mx12 = -1e30f, mx21 = -1e30f;
#pragma unroll
    for (int i = 0; i < PER; i++) {
        v12[i] = p12[t + i * 256];
        v21[i] = p21[t + i * 256];
        mx12 = fmaxf(mx12, v12[i]);
        mx21 = fmaxf(mx21, v21[i]);
    }
    __shared__ float red[2][8];
#pragma unroll
    for (int o = 16; o > 0; o >>= 1) {
        mx12 = fmaxf(mx12, __shfl_xor_sync(0xffffffffu, mx12, o));
        mx21 = fmaxf(mx21, __shfl_xor_sync(0xffffffffu, mx21, o));
    }
    if ((t & 31) == 0) { red[0][t >> 5] = mx12; red[1][t >> 5] = mx21; }
    __syncthreads();
    mx12 = red[0][0]; mx21 = red[1][0];
#pragma unroll
    for (int w = 1; w < 8; w++) {
        mx12 = fmaxf(mx12, red[0][w]);
        mx21 = fmaxf(mx21, red[1][w]);
    }
    __syncthreads();

    float s12 = 0.0f, s21 = 0.0f;
#pragma unroll
    for (int i = 0; i < PER; i++) {
        v12[i] = __expf(v12[i] - mx12);
        v21[i] = __expf(v21[i] - mx21);
        s12 += v12[i]; s21 += v21[i];
    }
#pragma unroll
    for (int o = 16; o > 0; o >>= 1) {
        s12 += __shfl_xor_sync(0xffffffffu, s12, o);
        s21 += __shfl_xor_sync(0xffffffffu, s21, o);
    }
    if ((t & 31) == 0) { red[0][t >> 5] = s12; red[1][t >> 5] = s21; }
    __syncthreads();
    s12 = red[0][0]; s21 = red[1][0];
#pragma unroll
    for (int w = 1; w < 8; w++) { s12 += red[0][w]; s21 += red[1][w]; }

    const float i12 = 1.0f / s12;
    const float i21 = 1.0f / s21;
#pragma unroll
    for (int i = 0; i < PER; i++) {
        float att = fabsf(v12[i] * i12 - v21[i] * i21);
        bf16 h = __float2bfloat16(att);
        oh[t + i * 256] = h;
        ol[t + i * 256] = __float2bfloat16(att - __bfloat162float(h));
    }
}

// ================= HMMA bf16 multi-term GEMM, 3-stage cp.async =============
// C[m,n] = sum_t sum_k A_t[m,k] * B_t[n,k]   (A, B K-major bf16)
// BM=BN=128, BK=32, 8 warps (4M x 2N), warp tile 32x64.
// BIASMODE: 0 none, 1 per-row bias[m]*g_scal[2], 2 per-col bias[n].
// EPI: 0 fp32 C, 1 bf16 hi/lo pair (Chi, Clo).
// SWAP: m0 from blockIdx.x (adjacent CTAs share B tiles -> L2 reuse).

#define SM_STRIDE 40                  // halves per smem row (80B, conflict-free)
#define STAGE_H   (128 * SM_STRIDE)   // halves per operand per stage
#define STAGE_B   (2 * STAGE_H * 2)   // bytes per stage (A+B) = 20480
#define SMEM_DYN  (3 * STAGE_B)       // 61440

__device__ __forceinline__ uint32_t smem_u32(const void* p) {
    uint32_t a;
    asm("{ .reg .u64 t; cvta.to.shared.u64 t, %1; cvt.u32.u64 %0, t; }" : "=r"(a) : "l"(p));
    return a;
}
__device__ __forceinline__ void cp16(uint32_t dst, const void* src) {
    asm volatile("cp.async.cg.shared.global [%0], [%1], 16;" :: "r"(dst), "l"(src));
}
__device__ __forceinline__ void ldsm4(uint32_t* r, uint32_t addr) {
    asm volatile("ldmatrix.sync.aligned.m8n8.x4.shared.b16 {%0,%1,%2,%3}, [%4];"
                 : "=r"(r[0]), "=r"(r[1]), "=r"(r[2]), "=r"(r[3]) : "r"(addr));
}
__device__ __forceinline__ void mma16816(float* d, const uint32_t* a, const uint32_t* b) {
    asm volatile(
        "mma.sync.aligned.m16n8k16.row.col.f32.bf16.bf16.f32 "
        "{%0,%1,%2,%3}, {%4,%5,%6,%7}, {%8,%9}, {%0,%1,%2,%3};"
        : "+f"(d[0]), "+f"(d[1]), "+f"(d[2]), "+f"(d[3])
        : "r"(a[0]), "r"(a[1]), "r"(a[2]), "r"(a[3]), "r"(b[0]), "r"(b[1]));
}

template<int BIASMODE, int EPI, bool SWAP>
__global__ void __launch_bounds__(256, 2) hgemm_kernel(
    const bf16* __restrict__ a0, const bf16* __restrict__ a1, const bf16* __restrict__ a2,
    const bf16* __restrict__ b0, const bf16* __restrict__ b1, const bf16* __restrict__ b2,
    int ktPerTerm, int nkt, int lda, int ldb, long bsA, long bsB,
    float* __restrict__ C, bf16* __restrict__ Chi, bf16* __restrict__ Clo,
    int ldc, long bsC, const float* __restrict__ bias)
{
    extern __shared__ __align__(16) bf16 dsm[];

    const int tid = threadIdx.x;
    const int wid = tid >> 5;
    const int lane = tid & 31;
    const int wm = wid >> 1;
    const int wn = wid & 1;
    const int m0 = (SWAP ? blockIdx.x : blockIdx.y) * 128;
    const int n0 = (SWAP ? blockIdx.y : blockIdx.x) * 128;
    const int z  = blockIdx.z;

    const uint32_t s0 = smem_u32(dsm);

    float acc[2][8][4];
#pragma unroll
    for (int i = 0; i < 2; i++)
#pragma unroll
        for (int j = 0; j < 8; j++)
#pragma unroll
            for (int q = 0; q < 4; q++) acc[i][j][q] = 0.0f;

    const int lrow0 = tid >> 2;
    const int lch0  = tid & 3;
    auto load_tile = [&](int g, int slot) {
        const int t  = g / ktPerTerm;
        const int k0 = (g - t * ktPerTerm) * 32;
        const bf16* Ap = (t == 0 ? a0 : (t == 1 ? a1 : a2)) + z * bsA + (long)m0 * lda + k0;
        const bf16* Bp = (t == 0 ? b0 : (t == 1 ? b1 : b2)) + z * bsB + (long)n0 * ldb + k0;
        const uint32_t da = s0 + slot * STAGE_B;
        const uint32_t db = da + STAGE_H * 2;
#pragma unroll
        for (int i = 0; i < 2; i++) {
            int row = lrow0 + i * 64;
            cp16(da + row * 80 + lch0 * 16, Ap + (long)row * lda + lch0 * 8);
            cp16(db + row * 80 + lch0 * 16, Bp + (long)row * ldb + lch0 * 8);
        }
        asm volatile("cp.async.commit_group;");
    };

    load_tile(0, 0);
    if (nkt > 1) load_tile(1, 1);

    int slot = 0;
    for (int g = 0; g < nkt; g++) {
        if (g + 1 < nkt) asm volatile("cp.async.wait_group 1;");
        else             asm volatile("cp.async.wait_group 0;");
        __syncthreads();

        if (g + 2 < nkt) {
            int ns = slot + 2; if (ns >= 3) ns -= 3;
            load_tile(g + 2, ns);
        }

        const uint32_t da = s0 + slot * STAGE_B;
        const uint32_t db = da + STAGE_H * 2;
#pragma unroll
        for (int ks = 0; ks < 2; ks++) {
            uint32_t af[2][4];
#pragma unroll
            for (int mt = 0; mt < 2; mt++) {
                int row = wm * 32 + mt * 16 + (lane & 15);
                int kc  = ks * 16 + (lane >> 4) * 8;
                ldsm4(af[mt], da + row * 80 + kc * 2);
            }
            uint32_t bfr[4][4];
#pragma unroll
            for (int p = 0; p < 4; p++) {
                int row = wn * 64 + p * 16 + (lane >> 4) * 8 + (lane & 7);
                int kc  = ks * 16 + ((lane >> 3) & 1) * 8;
                ldsm4(bfr[p], db + row * 80 + kc * 2);
            }
#pragma unroll
            for (int mt = 0; mt < 2; mt++)
#pragma unroll
                for (int p = 0; p < 4; p++) {
                    mma16816(acc[mt][2 * p],     af[mt], &bfr[p][0]);
                    mma16816(acc[mt][2 * p + 1], af[mt], &bfr[p][2]);
                }
        }
        slot++; if (slot >= 3) slot = 0;
        __syncthreads();
    }

    // epilogue
#pragma unroll
    for (int mt = 0; mt < 2; mt++) {
        const int mA = m0 + wm * 32 + mt * 16 + (lane >> 2);
        float bvA = 0.0f, bvB = 0.0f;
        if (BIASMODE == 1) { bvA = bias[mA] * g_scal[2]; bvB = bias[mA + 8] * g_scal[2]; }
#pragma unroll
        for (int nt = 0; nt < 8; nt++) {
            const int n = n0 + wn * 64 + nt * 8 + (lane & 3) * 2;
            float c0 = acc[mt][nt][0], c1 = acc[mt][nt][1];
            float c2 = acc[mt][nt][2], c3 = acc[mt][nt][3];
            if (BIASMODE == 1) { c0 += bvA; c1 += bvA; c2 += bvB; c3 += bvB; }
            if (BIASMODE == 2) {
                float b0v = bias[n], b1v = bias[n + 1];
                c0 += b0v; c1 += b1v; c2 += b0v; c3 += b1v;
            }
            if (EPI == 0) {
                float* Cz = C + (long)z * bsC;
                *(float2*)(Cz + (long)mA * ldc + n)       = make_float2(c0, c1);
                *(float2*)(Cz + (long)(mA + 8) * ldc + n) = make_float2(c2, c3);
            } else {
                bf16* Hz = Chi + (long)z * bsC;
                bf16* Lz = Clo + (long)z * bsC;
                bf16 h0 = __float2bfloat16(c0), h1 = __float2bfloat16(c1);
                bf16 h2 = __float2bfloat16(c2), h3 = __float2bfloat16(c3);
                __nv_bfloat162 H0; H0.x = h0; H0.y = h1;
                __nv_bfloat162 H1; H1.x = h2; H1.y = h3;
                __nv_bfloat162 L0;
                L0.x = __float2bfloat16(c0 - __bfloat162float(h0));
                L0.y = __float2bfloat16(c1 - __bfloat162float(h1));
                __nv_bfloat162 L1;
                L1.x = __float2bfloat16(c2 - __bfloat162float(h2));
                L1.y = __float2bfloat16(c3 - __bfloat162float(h3));
                *(__nv_bfloat162*)(Hz + (long)mA * ldc + n)       = H0;
                *(__nv_bfloat162*)(Hz + (long)(mA + 8) * ldc + n) = H1;
                *(__nv_bfloat162*)(Lz + (long)mA * ldc + n)       = L0;
                *(__nv_bfloat162*)(Lz + (long)(mA + 8) * ldc + n) = L1;
            }
        }
    }
}

// ---------------- launch ----------------
extern "C" void kernel_launch(void* const* d_in, const int* in_sizes, int n_in,
                              void* d_out, int out_size) {
    const float* x1    = (const float*)d_in[0];
    const float* x2    = (const float*)d_in[1];
    const float* Wb    = (const float*)d_in[2];
    const float* bb    = (const float*)d_in[3];
    const float* Wc    = (const float*)d_in[4];
    const float* bc    = (const float*)d_in[5];
    const float* Wdd   = (const float*)d_in[6];
    const float* bd    = (const float*)d_in[7];
    const float* alpha = (const float*)d_in[8];
    const float* beta  = (const float*)d_in[9];
    float* out = (float*)d_out;

    bf16 *xTh, *xTl, *xcTh, *xcTl, *Wbch, *Wbcl, *Wdh, *Wdl, *Ph, *Pl, *Fh, *Fl, *Ah, *Al;
    float *S12, *S21, *bias2;
    cudaGetSymbolAddress((void**)&xTh,  g_xTh);
    cudaGetSymbolAddress((void**)&xTl,  g_xTl);
    cudaGetSymbolAddress((void**)&xcTh, g_xcTh);
    cudaGetSymbolAddress((void**)&xcTl, g_xcTl);
    cudaGetSymbolAddress((void**)&Wbch, g_Wbch);
    cudaGetSymbolAddress((void**)&Wbcl, g_Wbcl);
    cudaGetSymbolAddress((void**)&Wdh,  g_Wdh);
    cudaGetSymbolAddress((void**)&Wdl,  g_Wdl);
    cudaGetSymbolAddress((void**)&Ph,   g_Ph);
    cudaGetSymbolAddress((void**)&Pl,   g_Pl);
    cudaGetSymbolAddress((void**)&Fh,   g_Fh);
    cudaGetSymbolAddress((void**)&Fl,   g_Fl);
    cudaGetSymbolAddress((void**)&S12,  g_S12);
    cudaGetSymbolAddress((void**)&S21,  g_S21);
    cudaGetSymbolAddress((void**)&Ah,   g_Ah);
    cudaGetSymbolAddress((void**)&Al,   g_Al);
    cudaGetSymbolAddress((void**)&bias2, g_bias2);

    cudaFuncSetAttribute(hgemm_kernel<2, 1, false>,
                         cudaFuncAttributeMaxDynamicSharedMemorySize, SMEM_DYN);
    cudaFuncSetAttribute(hgemm_kernel<1, 1, false>,
                         cudaFuncAttributeMaxDynamicSharedMemorySize, SMEM_DYN);
    cudaFuncSetAttribute(hgemm_kernel<0, 0, false>,
                         cudaFuncAttributeMaxDynamicSharedMemorySize, SMEM_DYN);
    cudaFuncSetAttribute(hgemm_kernel<0, 0, true>,
                         cudaFuncAttributeMaxDynamicSharedMemorySize, SMEM_DYN);

    prep_kernel<<<1, 128>>>(bb, bc, alpha, beta);

    dim3 gT(NPIX / 32, CH / 32, BATCH);
    transcomb_kernel<<<gT, dim3(32, 8)>>>(x1, x2);

    wbc_split_kernel<<<(128 * CH + 255) / 256, 256>>>(Wb, Wc);
    split_kernel<<<(CH * CH + 255) / 256, 256>>>(Wdd, Wdh, Wdl, CH * CH);

    const long bsXT = (long)NPIX * CH;
    const long bsP  = (long)NPIX * 128;
    const long bsF  = (long)CH * NPIX;
    const long bsS  = (long)NPIX * NPIX;

    // P^T = x^T @ Wbc^T (M=4096, N=128, K=512), z=which*2+b, bias per-col, bf16 epi
    hgemm_kernel<2, 1, false><<<dim3(1, NPIX / 128, 4), 256, SMEM_DYN>>>(
        xTh, xTl, xTh,  Wbch, Wbch, Wbcl,
        CH / 32, 3 * CH / 32, CH, CH, bsXT, 0L,
        nullptr, Ph, Pl, 128, bsP, bias2);

    // F = Wdd @ xc + (a+b)*bd (M=512, N=4096, K=512), bias per-row, bf16 epi
    hgemm_kernel<1, 1, false><<<dim3(NPIX / 128, CH / 128, BATCH), 256, SMEM_DYN>>>(
        Wdh, Wdl, Wdh,  xcTh, xcTh, xcTl,
        CH / 32, 3 * CH / 32, CH, CH, 0L, bsXT,
        nullptr, Fh, Fl, NPIX, bsF, bd);

    // logits S12[n,m] = A1[n,:]·B2[m,:]  (M=N=4096, K=64)
    dim3 gS(NPIX / 128, NPIX / 128, BATCH);
    hgemm_kernel<0, 0, false><<<gS, 256, SMEM_DYN>>>(
        Ph, Pl, Ph,  Ph + 2 * bsP + 64, Ph + 2 * bsP + 64, Pl + 2 * bsP + 64,
        2, 6, 128, 128, bsP, bsP,
        S12, nullptr, nullptr, NPIX, bsS, nullptr);
    hgemm_kernel<0, 0, false><<<gS, 256, SMEM_DYN>>>(
        Ph + 2 * bsP, Pl + 2 * bsP, Ph + 2 * bsP,  Ph + 64, Ph + 64, Pl + 64,
        2, 6, 128, 128, bsP, bsP,
        S21, nullptr, nullptr, NPIX, bsS, nullptr);

    // att = |softmax(S12)-softmax(S21)| -> bf16 hi/lo
    softdiff_kernel<<<BATCH * NPIX, 256>>>();

    // out[c,n] = sum_m F[c,m]*att[n,m]  (M=512, N=4096, K=3*4096)
    // SWAP grid: x walks the 4 c-blocks so att row-blocks are L2-shared.
    hgemm_kernel<0, 0, true><<<dim3(CH / 128, NPIX / 128, BATCH), 256, SMEM_DYN>>>(
        Fh, Fl, Fh,  Ah, Ah, Al,
        NPIX / 32, 3 * NPIX / 32, NPIX, NPIX, bsF, bsS,
        out, nullptr, nullptr, NPIX, bsF, nullptr);
}